// round 15
// baseline (speedup 1.0000x reference)
#include <cuda_runtime.h>
#include <cuda_fp16.h>
#include <cstdint>
#include <math.h>

// ---------------------------------------------------------------------------
// AttentionActPrune: full MHA block. B=16, S=1024, d=1024, H=16, Dh=64.
// Round 14: attention — 256-row q-blocks (256 thr, 8 warps; staging+barriers
//           per q-row halved) and exp2 softmax with log2e folded into the Q
//           scale. GEMM frozen from R13 (LDSM + 4-stage cp.async).
// ---------------------------------------------------------------------------

#define BATCH   16
#define SEQ     1024
#define DMODEL  1024
#define NHEAD   16
#define DHEAD   64
#define MROWS   (BATCH * SEQ)          // 16384
#define NQKV    (3 * DMODEL)           // 3072

__device__ __half g_QKVh[(size_t)MROWS * NQKV];
__device__ __half g_Ch[(size_t)MROWS * DMODEL];
__device__ __half g_Xh[(size_t)MROWS * DMODEL];
__device__ __half g_Wh[4][(size_t)DMODEL * DMODEL];
__device__ float  g_biasQKV[NQKV];

__device__ __forceinline__ void mma_fp16(float* c, uint32_t a0, uint32_t a1,
                                         uint32_t a2, uint32_t a3,
                                         uint32_t b0, uint32_t b1) {
    asm volatile(
        "mma.sync.aligned.m16n8k16.row.col.f32.f16.f16.f32 "
        "{%0,%1,%2,%3}, {%4,%5,%6,%7}, {%8,%9}, {%0,%1,%2,%3};"
        : "+f"(c[0]), "+f"(c[1]), "+f"(c[2]), "+f"(c[3])
        : "r"(a0), "r"(a1), "r"(a2), "r"(a3), "r"(b0), "r"(b1));
}

__device__ __forceinline__ void ldsm_x4(uint32_t& r0, uint32_t& r1,
                                        uint32_t& r2, uint32_t& r3,
                                        uint32_t addr) {
    asm volatile("ldmatrix.sync.aligned.m8n8.x4.shared.b16 {%0,%1,%2,%3}, [%4];"
                 : "=r"(r0), "=r"(r1), "=r"(r2), "=r"(r3) : "r"(addr));
}

__device__ __forceinline__ uint32_t pack_h2(float lo, float hi) {
    __half2 h = __floats2half2_rn(lo, hi);
    return *(uint32_t*)&h;
}

__device__ __forceinline__ float fexp2(float x) {
    float y;
    asm("ex2.approx.f32 %0, %1;" : "=f"(y) : "f"(x));
    return y;
}

__device__ __forceinline__ uint32_t smem_u32ptr(const void* p) {
    uint32_t a;
    asm("{ .reg .u64 t; cvta.to.shared.u64 t, %1; cvt.u32.u64 %0, t; }"
        : "=r"(a) : "l"(p));
    return a;
}

__device__ __forceinline__ void cp_async16(uint32_t s, const void* g) {
    asm volatile("cp.async.cg.shared.global [%0], [%1], 16;" :: "r"(s), "l"(g));
}
#define CP_COMMIT()  asm volatile("cp.async.commit_group;" ::: "memory")
#define CP_WAIT(n)   asm volatile("cp.async.wait_group %0;" :: "n"(n) : "memory")

// ---------------------------------------------------------------------------
// fp32 -> fp16 conversion pass
// ---------------------------------------------------------------------------
__global__ __launch_bounds__(256)
void cvt_f32_f16(const float* __restrict__ in, __half* __restrict__ out) {
    size_t i = ((size_t)blockIdx.x * 256 + threadIdx.x) * 4;
    float4 v = *(const float4*)(in + i);
    uint2 o = make_uint2(pack_h2(v.x, v.y), pack_h2(v.z, v.w));
    *(uint2*)(out + i) = o;
}

// ---------------------------------------------------------------------------
// fp16 GEMM (NT), 4-stage cp.async + LDSM fragments, single barrier/iter.
// (unchanged from R13)
// ---------------------------------------------------------------------------
#define GSTR 20
#define GST_U32    (128 * GSTR)
#define GSTAGE_U32 (2 * GST_U32)
#define GEMM_SMEM_BYTES (4 * GSTAGE_U32 * 4)   // 81920 B

template<int OUT32>
__global__ __launch_bounds__(128)
void gemm_f16_nt(const __half* __restrict__ A, const __half* __restrict__ B,
                 const float* __restrict__ bias, void* __restrict__ Cout,
                 int M, int N, int K)
{
    extern __shared__ uint32_t gsm[];
    const uint32_t smem_base = smem_u32ptr(gsm);

    const int tid  = threadIdx.x;
    const int wid  = tid >> 5;
    const int lane = tid & 31;
    const int g    = lane >> 2;
    const int tg   = lane & 3;
    const int warp_m = wid & 1;
    const int warp_n = wid >> 1;
    const int bm = blockIdx.y * 128;
    const int bn = blockIdx.x * 128;

    const int sr = tid >> 2;
    const int sc = tid & 3;

    auto issue_stage = [&](int stage, int k0) {
        const uint32_t sa = smem_base + (uint32_t)stage * GSTAGE_U32 * 4;
        const uint32_t sb = sa + GST_U32 * 4;
#pragma unroll
        for (int i = 0; i < 4; i++) {
            const int r = sr + i * 32;
            const uint32_t off = (uint32_t)(r * GSTR + sc * 4) * 4;
            cp_async16(sa + off, A + (size_t)(bm + r) * K + k0 + sc * 8);
            cp_async16(sb + off, B + (size_t)(bn + r) * K + k0 + sc * 8);
        }
        CP_COMMIT();
    };

    const uint32_t a_lane_off =
        (uint32_t)((warp_m * 64 + (lane & 15)) * GSTR) * 4 + (lane >> 4) * 16;
    const uint32_t b_lane_off =
        (uint32_t)((warp_n * 64 + (lane & 7) + ((lane & 16) ? 8 : 0)) * GSTR) * 4
        + ((lane >> 3) & 1) * 16;

    const int nkc = K / 32;
    issue_stage(0, 0);
    issue_stage(1, 32);

    float acc[4][8][4];
#pragma unroll
    for (int i = 0; i < 4; i++)
#pragma unroll
        for (int j = 0; j < 8; j++)
#pragma unroll
            for (int q = 0; q < 4; q++) acc[i][j][q] = 0.f;

    for (int kc = 0; kc < nkc; kc++) {
        if (kc + 2 < nkc) issue_stage((kc + 2) & 3, (kc + 2) * 32);
        else              CP_COMMIT();
        CP_WAIT(2);
        __syncthreads();

        const uint32_t stA = smem_base + (uint32_t)(kc & 3) * GSTAGE_U32 * 4;
        const uint32_t stB = stA + GST_U32 * 4;

#pragma unroll
        for (int ks = 0; ks < 2; ks++) {
            uint32_t af[4][4];
#pragma unroll
            for (int mt = 0; mt < 4; mt++)
                ldsm_x4(af[mt][0], af[mt][1], af[mt][2], af[mt][3],
                        stA + a_lane_off + (uint32_t)(mt * 16 * GSTR) * 4 + ks * 32);
            uint32_t bfr[4][4];
#pragma unroll
            for (int j = 0; j < 4; j++)
                ldsm_x4(bfr[j][0], bfr[j][1], bfr[j][2], bfr[j][3],
                        stB + b_lane_off + (uint32_t)(j * 16 * GSTR) * 4 + ks * 32);
#pragma unroll
            for (int mt = 0; mt < 4; mt++)
#pragma unroll
                for (int nt = 0; nt < 8; nt++)
                    mma_fp16(acc[mt][nt],
                             af[mt][0], af[mt][1], af[mt][2], af[mt][3],
                             bfr[nt >> 1][(nt & 1) * 2],
                             bfr[nt >> 1][(nt & 1) * 2 + 1]);
        }
    }

#pragma unroll
    for (int mt = 0; mt < 4; mt++) {
        const int row0 = bm + warp_m * 64 + mt * 16 + g;
#pragma unroll
        for (int nt = 0; nt < 8; nt++) {
            const int col = bn + warp_n * 64 + nt * 8 + 2 * tg;
            const float b0 = bias[col], b1 = bias[col + 1];
            if (OUT32) {
                float* C = (float*)Cout;
                *(float2*)(C + (size_t)row0 * N + col) =
                    make_float2(acc[mt][nt][0] + b0, acc[mt][nt][1] + b1);
                *(float2*)(C + (size_t)(row0 + 8) * N + col) =
                    make_float2(acc[mt][nt][2] + b0, acc[mt][nt][3] + b1);
            } else {
                __half* C = (__half*)Cout;
                *(uint32_t*)(C + (size_t)row0 * N + col) =
                    pack_h2(acc[mt][nt][0] + b0, acc[mt][nt][1] + b1);
                *(uint32_t*)(C + (size_t)(row0 + 8) * N + col) =
                    pack_h2(acc[mt][nt][2] + b0, acc[mt][nt][3] + b1);
            }
        }
    }
}

// ---------------------------------------------------------------------------
// fp16 flash attention: 256 q-rows/CTA, 256 threads (8 warps x 32 rows).
// Staging + barriers per q-row halved vs 128-row blocks. exp2 softmax with
// log2e folded into Q scale. LDSM for Q/K fragments; PV register-P path.
// ---------------------------------------------------------------------------
#define QROWS 256
#define QSTR 44
#define KSTR 44
#define VSTR 42
#define Q_U32 (QROWS * QSTR)           // 11264
#define K_U32 (64 * KSTR)              // 2816 per buffer
#define V_U32 (64 * VSTR)              // 2688 per buffer
#define ATT_SMEM_U32 (Q_U32 + 2 * K_U32 + 2 * V_U32)   // 22272 u32 = 89088 B

__global__ __launch_bounds__(256, 1)
void attention_tc(const __half* __restrict__ QKV, __half* __restrict__ C)
{
    extern __shared__ uint32_t sm[];
    uint32_t* Qs = sm;
    uint32_t* Vt = sm + Q_U32 + 2 * K_U32;
    const uint32_t smem_base = smem_u32ptr(sm);
    const uint32_t ks_base_b = smem_base + Q_U32 * 4;

    const int tid  = threadIdx.x;
    const int wid  = tid >> 5;               // 0..7
    const int lane = tid & 31;
    const int g    = lane >> 2;
    const int tg   = lane & 3;
    const int qb = blockIdx.x;               // 0..3
    const int h  = blockIdx.y;
    const int b  = blockIdx.z;
    const size_t baseQ = (size_t)b * SEQ * NQKV + h * DHEAD;
    const size_t baseK = baseQ + DMODEL;
    const size_t baseV = baseQ + 2 * DMODEL;
    const size_t baseC = (size_t)b * SEQ * DMODEL + h * DHEAD;
    const int wr = wid * 32;                 // warp's first q row

    // scale = (1/8) * log2(e): softmax done in exp2 domain
    const __half2 hscale = __floats2half2_rn(0.18033688f, 0.18033688f);

    // K staging: 512 16B-chunks, 2 per thread
    const int kr = tid >> 3;                 // 0..31 (key base; +32 per i)
    const int kcnk = tid & 7;
    auto issue_K = [&](int kb, int buf) {
        const uint32_t kd = ks_base_b + (uint32_t)buf * K_U32 * 4;
#pragma unroll
        for (int i = 0; i < 2; i++) {
            const int key = kr + i * 32;
            cp_async16(kd + (uint32_t)(key * KSTR + kcnk * 4) * 4,
                       QKV + baseK + (size_t)(kb * 64 + key) * NQKV + kcnk * 8);
        }
        CP_COMMIT();
    };

    // V prefetch: 512 tasks, 2 per thread
    const int vp_p  = tid >> 4;              // 0..15 (pair base; +16 per i)
    const int vp_dc = tid & 15;
    auto ldg_V = [&](int kb, uint2* ea, uint2* eb) {
#pragma unroll
        for (int i = 0; i < 2; i++) {
            const int p = vp_p + i * 16;
            const __half* vb = QKV + baseV + (size_t)(kb * 64 + 2 * p) * NQKV + vp_dc * 4;
            ea[i] = *(const uint2*)(vb);
            eb[i] = *(const uint2*)(vb + NQKV);
        }
    };
    auto sts_V = [&](int buf, const uint2* ea, const uint2* eb) {
        uint32_t* vd = Vt + buf * V_U32;
#pragma unroll
        for (int i = 0; i < 2; i++) {
            const int p = vp_p + i * 16;
            __half2 ax = *(__half2*)&ea[i].x, ay = *(__half2*)&ea[i].y;
            __half2 bx = *(__half2*)&eb[i].x, by = *(__half2*)&eb[i].y;
            int pos = (p & ~7) + 2 * (p & 3) + ((p >> 2) & 1);
            __half2 o0 = __lows2half2(ax, bx), o1 = __highs2half2(ax, bx);
            __half2 o2 = __lows2half2(ay, by), o3 = __highs2half2(ay, by);
            vd[(vp_dc * 4 + 0) * VSTR + pos] = *(uint32_t*)&o0;
            vd[(vp_dc * 4 + 1) * VSTR + pos] = *(uint32_t*)&o1;
            vd[(vp_dc * 4 + 2) * VSTR + pos] = *(uint32_t*)&o2;
            vd[(vp_dc * 4 + 3) * VSTR + pos] = *(uint32_t*)&o3;
        }
    };

    // ---- prologue: issue K0, stage V0, stage Q (scaled) ----
    issue_K(0, 0);
    {
        uint2 ea[2], eb[2];
        ldg_V(0, ea, eb);
        sts_V(0, ea, eb);
    }
#pragma unroll
    for (int i = 0; i < 16; i++) {
        int t = tid + i * 256;               // 0..4095
        int r = t >> 4, c = t & 15;
        uint2 v = *(const uint2*)(QKV + baseQ + (size_t)(qb * QROWS + r) * NQKV + c * 4);
        __half2 a = __hmul2(*(__half2*)&v.x, hscale);
        __half2 bb = __hmul2(*(__half2*)&v.y, hscale);
        Qs[r * QSTR + c * 2 + 0] = *(uint32_t*)&a;
        Qs[r * QSTR + c * 2 + 1] = *(uint32_t*)&bb;
    }
    CP_WAIT(0);
    __syncthreads();

    // ---- hoist Q fragments via LDSM ----
    const uint32_t q_lane_off =
        (uint32_t)((wr + (lane & 15)) * QSTR) * 4 + (lane >> 4) * 16;
    uint32_t qf[2][4][4];
#pragma unroll
    for (int mt = 0; mt < 2; mt++)
#pragma unroll
        for (int ks = 0; ks < 4; ks++)
            ldsm_x4(qf[mt][ks][0], qf[mt][ks][1], qf[mt][ks][2], qf[mt][ks][3],
                    smem_base + q_lane_off + (uint32_t)(mt * 16 * QSTR) * 4 + ks * 32);

    const uint32_t k_lane_off =
        (uint32_t)(((lane & 7) + ((lane & 16) ? 8 : 0)) * KSTR) * 4
        + ((lane >> 3) & 1) * 16;

    float o[2][8][4];
#pragma unroll
    for (int mt = 0; mt < 2; mt++)
#pragma unroll
        for (int nt = 0; nt < 8; nt++)
#pragma unroll
            for (int q = 0; q < 4; q++) o[mt][nt][q] = 0.f;
    float mrow[2][2], lrow[2][2];
#pragma unroll
    for (int mt = 0; mt < 2; mt++) {
        mrow[mt][0] = mrow[mt][1] = -1e30f;
        lrow[mt][0] = lrow[mt][1] = 0.f;
    }

    for (int kb = 0; kb < SEQ / 64; kb++) {
        const int nb = (kb + 1) & 1;
        const bool more = (kb + 1 < SEQ / 64);
        if (more) issue_K(kb + 1, nb);
        else      CP_COMMIT();
        uint2 ea[2], eb[2];
        ldg_V(more ? kb + 1 : kb, ea, eb);

        const uint32_t kbuf = ks_base_b + (uint32_t)(kb & 1) * K_U32 * 4;
        const uint32_t* Vb = Vt + (kb & 1) * V_U32;

        // ---- S = Q @ K^T (exp2-domain scores) ----
        float s[2][8][4];
#pragma unroll
        for (int mt = 0; mt < 2; mt++)
#pragma unroll
            for (int nt = 0; nt < 8; nt++)
#pragma unroll
                for (int q = 0; q < 4; q++) s[mt][nt][q] = 0.f;

#pragma unroll
        for (int ks = 0; ks < 4; ks++) {
            uint32_t kf[4][4];
#pragma unroll
            for (int j = 0; j < 4; j++)
                ldsm_x4(kf[j][0], kf[j][1], kf[j][2], kf[j][3],
                        kbuf + k_lane_off + (uint32_t)(j * 16 * KSTR) * 4 + ks * 32);
#pragma unroll
            for (int nt = 0; nt < 8; nt++)
#pragma unroll
                for (int mt = 0; mt < 2; mt++)
                    mma_fp16(s[mt][nt],
                             qf[mt][ks][0], qf[mt][ks][1],
                             qf[mt][ks][2], qf[mt][ks][3],
                             kf[nt >> 1][(nt & 1) * 2],
                             kf[nt >> 1][(nt & 1) * 2 + 1]);
        }

        // ---- online softmax (exp2); P packed to half2 in registers ----
        uint32_t ph[2][8][2];
#pragma unroll
        for (int mt = 0; mt < 2; mt++) {
            float mx0 = -1e30f, mx1 = -1e30f;
#pragma unroll
            for (int nt = 0; nt < 8; nt++) {
                mx0 = fmaxf(mx0, fmaxf(s[mt][nt][0], s[mt][nt][1]));
                mx1 = fmaxf(mx1, fmaxf(s[mt][nt][2], s[mt][nt][3]));
            }
            mx0 = fmaxf(mx0, __shfl_xor_sync(0xffffffffu, mx0, 1));
            mx0 = fmaxf(mx0, __shfl_xor_sync(0xffffffffu, mx0, 2));
            mx1 = fmaxf(mx1, __shfl_xor_sync(0xffffffffu, mx1, 1));
            mx1 = fmaxf(mx1, __shfl_xor_sync(0xffffffffu, mx1, 2));
            const float mn0 = fmaxf(mrow[mt][0], mx0);
            const float mn1 = fmaxf(mrow[mt][1], mx1);
            const float al0 = fexp2(mrow[mt][0] - mn0);
            const float al1 = fexp2(mrow[mt][1] - mn1);
            mrow[mt][0] = mn0; mrow[mt][1] = mn1;

            float sum0 = 0.f, sum1 = 0.f;
#pragma unroll
            for (int nt = 0; nt < 8; nt++) {
                float p0 = fexp2(s[mt][nt][0] - mn0);
                float p1 = fexp2(s[mt][nt][1] - mn0);
                float p2 = fexp2(s[mt][nt][2] - mn1);
                float p3 = fexp2(s[mt][nt][3] - mn1);
                sum0 += p0 + p1; sum1 += p2 + p3;
                ph[mt][nt][0] = pack_h2(p0, p1);
                ph[mt][nt][1] = pack_h2(p2, p3);
                o[mt][nt][0] *= al0; o[mt][nt][1] *= al0;
                o[mt][nt][2] *= al1; o[mt][nt][3] *= al1;
            }
            sum0 += __shfl_xor_sync(0xffffffffu, sum0, 1);
            sum0 += __shfl_xor_sync(0xffffffffu, sum0, 2);
            sum1 += __shfl_xor_sync(0xffffffffu, sum1, 1);
            sum1 += __shfl_xor_sync(0xffffffffu, sum1, 2);
            lrow[mt][0] = lrow[mt][0] * al0 + sum0;
            lrow[mt][1] = lrow[mt][1] * al1 + sum1;
        }

        // ---- O += P @ V (register P; V pair-permutation matches ph) ----
#pragma unroll
        for (int kc = 0; kc < 4; kc++) {
            const int vcol = kc * 8 + 2 * tg;
#pragma unroll
            for (int nt = 0; nt < 8; nt++) {
                uint2 bf = *(const uint2*)&Vb[(nt * 8 + g) * VSTR + vcol];
#pragma unroll
                for (int mt = 0; mt < 2; mt++)
                    mma_fp16(o[mt][nt],
                             ph[mt][2 * kc][0], ph[mt][2 * kc][1],
                             ph[mt][2 * kc + 1][0], ph[mt][2 * kc + 1][1],
                             bf.x, bf.y);
            }
        }

        if (more) sts_V(nb, ea, eb);
        CP_WAIT(0);
        __syncthreads();
    }

    // ---- normalize + store ctx (half) ----
#pragma unroll
    for (int mt = 0; mt < 2; mt++) {
        const float li0 = 1.f / lrow[mt][0];
        const float li1 = 1.f / lrow[mt][1];
        const size_t r0 = baseC + (size_t)(qb * QROWS + wr + mt * 16 + g) * DMODEL;
        const size_t r1 = r0 + (size_t)8 * DMODEL;
#pragma unroll
        for (int nt = 0; nt < 8; nt++) {
            const int col = nt * 8 + 2 * tg;
            *(uint32_t*)(C + r0 + col) = pack_h2(o[mt][nt][0] * li0, o[mt][nt][1] * li0);
            *(uint32_t*)(C + r1 + col) = pack_h2(o[mt][nt][2] * li1, o[mt][nt][3] * li1);
        }
    }
}

// ---------------------------------------------------------------------------
// Launch
// ---------------------------------------------------------------------------
extern "C" void kernel_launch(void* const* d_in, const int* in_sizes, int n_in,
                              void* d_out, int out_size)
{
    const float* X  = (const float*)d_in[0];
    const float* Wq = (const float*)d_in[1];
    const float* bq = (const float*)d_in[2];
    const float* Wk = (const float*)d_in[3];
    const float* bk = (const float*)d_in[4];
    const float* Wv = (const float*)d_in[5];
    const float* bv = (const float*)d_in[6];
    const float* Wo = (const float*)d_in[7];
    const float* bo = (const float*)d_in[8];
    float* out = (float*)d_out;

    __half *QKVp, *Cp, *Xh, *Wh;
    float* biasQKV;
    cudaGetSymbolAddress((void**)&QKVp, g_QKVh);
    cudaGetSymbolAddress((void**)&Cp, g_Ch);
    cudaGetSymbolAddress((void**)&Xh, g_Xh);
    cudaGetSymbolAddress((void**)&Wh, g_Wh);
    cudaGetSymbolAddress((void**)&biasQKV, g_biasQKV);
    __half* Wh0 = Wh;
    __half* Wh3 = Wh + 3 * (size_t)DMODEL * DMODEL;

    static bool attr_set = false;
    if (!attr_set) {
        cudaFuncSetAttribute(attention_tc,
                             cudaFuncAttributeMaxDynamicSharedMemorySize,
                             ATT_SMEM_U32 * (int)sizeof(uint32_t));
        cudaFuncSetAttribute(gemm_f16_nt<0>,
                             cudaFuncAttributeMaxDynamicSharedMemorySize,
                             GEMM_SMEM_BYTES);
        cudaFuncSetAttribute(gemm_f16_nt<1>,
                             cudaFuncAttributeMaxDynamicSharedMemorySize,
                             GEMM_SMEM_BYTES);
        attr_set = true;
    }

    cudaMemcpyAsync(biasQKV,            bq, DMODEL * sizeof(float), cudaMemcpyDeviceToDevice);
    cudaMemcpyAsync(biasQKV + DMODEL,   bk, DMODEL * sizeof(float), cudaMemcpyDeviceToDevice);
    cudaMemcpyAsync(biasQKV + 2*DMODEL, bv, DMODEL * sizeof(float), cudaMemcpyDeviceToDevice);

    const int XBLK = (MROWS * DMODEL) / (256 * 4);
    const int WBLK = (DMODEL * DMODEL) / (256 * 4);
    cvt_f32_f16<<<XBLK, 256>>>(X,  Xh);
    cvt_f32_f16<<<WBLK, 256>>>(Wq, Wh0);
    cvt_f32_f16<<<WBLK, 256>>>(Wk, Wh0 + (size_t)DMODEL * DMODEL);
    cvt_f32_f16<<<WBLK, 256>>>(Wv, Wh0 + 2 * (size_t)DMODEL * DMODEL);
    cvt_f32_f16<<<WBLK, 256>>>(Wo, Wh3);

    dim3 qkv_grid(NQKV / 128, MROWS / 128);      // (24, 128)
    gemm_f16_nt<0><<<qkv_grid, 128, GEMM_SMEM_BYTES>>>(
        Xh, Wh0, biasQKV, QKVp, MROWS, NQKV, DMODEL);

    dim3 att_grid(SEQ / QROWS, NHEAD, BATCH);    // (4, 16, 16)
    attention_tc<<<att_grid, 256, ATT_SMEM_U32 * sizeof(uint32_t)>>>(QKVp, Cp);

    dim3 o_grid(DMODEL / 128, MROWS / 128);      // (8, 128)
    gemm_f16_nt<1><<<o_grid, 128, GEMM_SMEM_BYTES>>>(
        Cp, Wh3, bo, out, MROWS, DMODEL, DMODEL);
}

// round 17
// speedup vs baseline: 1.0284x; 1.0284x over previous
#include <cuda_runtime.h>
#include <cuda_fp16.h>
#include <cstdint>
#include <math.h>

// ---------------------------------------------------------------------------
// AttentionActPrune: full MHA block. B=16, S=1024, d=1024, H=16, Dh=64.
// Round 16: R13 attention shape (128-row q-blocks, 2 CTAs/SM) + exp2 softmax
//           only (log2e folded into Q scale). GEMM frozen from R13.
// ---------------------------------------------------------------------------

#define BATCH   16
#define SEQ     1024
#define DMODEL  1024
#define NHEAD   16
#define DHEAD   64
#define MROWS   (BATCH * SEQ)          // 16384
#define NQKV    (3 * DMODEL)           // 3072

__device__ __half g_QKVh[(size_t)MROWS * NQKV];
__device__ __half g_Ch[(size_t)MROWS * DMODEL];
__device__ __half g_Xh[(size_t)MROWS * DMODEL];
__device__ __half g_Wh[4][(size_t)DMODEL * DMODEL];
__device__ float  g_biasQKV[NQKV];

__device__ __forceinline__ void mma_fp16(float* c, uint32_t a0, uint32_t a1,
                                         uint32_t a2, uint32_t a3,
                                         uint32_t b0, uint32_t b1) {
    asm volatile(
        "mma.sync.aligned.m16n8k16.row.col.f32.f16.f16.f32 "
        "{%0,%1,%2,%3}, {%4,%5,%6,%7}, {%8,%9}, {%0,%1,%2,%3};"
        : "+f"(c[0]), "+f"(c[1]), "+f"(c[2]), "+f"(c[3])
        : "r"(a0), "r"(a1), "r"(a2), "r"(a3), "r"(b0), "r"(b1));
}

__device__ __forceinline__ void ldsm_x4(uint32_t& r0, uint32_t& r1,
                                        uint32_t& r2, uint32_t& r3,
                                        uint32_t addr) {
    asm volatile("ldmatrix.sync.aligned.m8n8.x4.shared.b16 {%0,%1,%2,%3}, [%4];"
                 : "=r"(r0), "=r"(r1), "=r"(r2), "=r"(r3) : "r"(addr));
}

__device__ __forceinline__ uint32_t pack_h2(float lo, float hi) {
    __half2 h = __floats2half2_rn(lo, hi);
    return *(uint32_t*)&h;
}

__device__ __forceinline__ float fexp2(float x) {
    float y;
    asm("ex2.approx.f32 %0, %1;" : "=f"(y) : "f"(x));
    return y;
}

__device__ __forceinline__ uint32_t smem_u32ptr(const void* p) {
    uint32_t a;
    asm("{ .reg .u64 t; cvta.to.shared.u64 t, %1; cvt.u32.u64 %0, t; }"
        : "=r"(a) : "l"(p));
    return a;
}

__device__ __forceinline__ void cp_async16(uint32_t s, const void* g) {
    asm volatile("cp.async.cg.shared.global [%0], [%1], 16;" :: "r"(s), "l"(g));
}
#define CP_COMMIT()  asm volatile("cp.async.commit_group;" ::: "memory")
#define CP_WAIT(n)   asm volatile("cp.async.wait_group %0;" :: "n"(n) : "memory")

// ---------------------------------------------------------------------------
// fp32 -> fp16 conversion pass
// ---------------------------------------------------------------------------
__global__ __launch_bounds__(256)
void cvt_f32_f16(const float* __restrict__ in, __half* __restrict__ out) {
    size_t i = ((size_t)blockIdx.x * 256 + threadIdx.x) * 4;
    float4 v = *(const float4*)(in + i);
    uint2 o = make_uint2(pack_h2(v.x, v.y), pack_h2(v.z, v.w));
    *(uint2*)(out + i) = o;
}

// ---------------------------------------------------------------------------
// fp16 GEMM (NT), 4-stage cp.async + LDSM fragments, single barrier/iter.
// (unchanged from R13)
// ---------------------------------------------------------------------------
#define GSTR 20
#define GST_U32    (128 * GSTR)
#define GSTAGE_U32 (2 * GST_U32)
#define GEMM_SMEM_BYTES (4 * GSTAGE_U32 * 4)   // 81920 B

template<int OUT32>
__global__ __launch_bounds__(128)
void gemm_f16_nt(const __half* __restrict__ A, const __half* __restrict__ B,
                 const float* __restrict__ bias, void* __restrict__ Cout,
                 int M, int N, int K)
{
    extern __shared__ uint32_t gsm[];
    const uint32_t smem_base = smem_u32ptr(gsm);

    const int tid  = threadIdx.x;
    const int wid  = tid >> 5;
    const int lane = tid & 31;
    const int g    = lane >> 2;
    const int tg   = lane & 3;
    const int warp_m = wid & 1;
    const int warp_n = wid >> 1;
    const int bm = blockIdx.y * 128;
    const int bn = blockIdx.x * 128;

    const int sr = tid >> 2;
    const int sc = tid & 3;

    auto issue_stage = [&](int stage, int k0) {
        const uint32_t sa = smem_base + (uint32_t)stage * GSTAGE_U32 * 4;
        const uint32_t sb = sa + GST_U32 * 4;
#pragma unroll
        for (int i = 0; i < 4; i++) {
            const int r = sr + i * 32;
            const uint32_t off = (uint32_t)(r * GSTR + sc * 4) * 4;
            cp_async16(sa + off, A + (size_t)(bm + r) * K + k0 + sc * 8);
            cp_async16(sb + off, B + (size_t)(bn + r) * K + k0 + sc * 8);
        }
        CP_COMMIT();
    };

    const uint32_t a_lane_off =
        (uint32_t)((warp_m * 64 + (lane & 15)) * GSTR) * 4 + (lane >> 4) * 16;
    const uint32_t b_lane_off =
        (uint32_t)((warp_n * 64 + (lane & 7) + ((lane & 16) ? 8 : 0)) * GSTR) * 4
        + ((lane >> 3) & 1) * 16;

    const int nkc = K / 32;
    issue_stage(0, 0);
    issue_stage(1, 32);

    float acc[4][8][4];
#pragma unroll
    for (int i = 0; i < 4; i++)
#pragma unroll
        for (int j = 0; j < 8; j++)
#pragma unroll
            for (int q = 0; q < 4; q++) acc[i][j][q] = 0.f;

    for (int kc = 0; kc < nkc; kc++) {
        if (kc + 2 < nkc) issue_stage((kc + 2) & 3, (kc + 2) * 32);
        else              CP_COMMIT();
        CP_WAIT(2);
        __syncthreads();

        const uint32_t stA = smem_base + (uint32_t)(kc & 3) * GSTAGE_U32 * 4;
        const uint32_t stB = stA + GST_U32 * 4;

#pragma unroll
        for (int ks = 0; ks < 2; ks++) {
            uint32_t af[4][4];
#pragma unroll
            for (int mt = 0; mt < 4; mt++)
                ldsm_x4(af[mt][0], af[mt][1], af[mt][2], af[mt][3],
                        stA + a_lane_off + (uint32_t)(mt * 16 * GSTR) * 4 + ks * 32);
            uint32_t bfr[4][4];
#pragma unroll
            for (int j = 0; j < 4; j++)
                ldsm_x4(bfr[j][0], bfr[j][1], bfr[j][2], bfr[j][3],
                        stB + b_lane_off + (uint32_t)(j * 16 * GSTR) * 4 + ks * 32);
#pragma unroll
            for (int mt = 0; mt < 4; mt++)
#pragma unroll
                for (int nt = 0; nt < 8; nt++)
                    mma_fp16(acc[mt][nt],
                             af[mt][0], af[mt][1], af[mt][2], af[mt][3],
                             bfr[nt >> 1][(nt & 1) * 2],
                             bfr[nt >> 1][(nt & 1) * 2 + 1]);
        }
    }

#pragma unroll
    for (int mt = 0; mt < 4; mt++) {
        const int row0 = bm + warp_m * 64 + mt * 16 + g;
#pragma unroll
        for (int nt = 0; nt < 8; nt++) {
            const int col = bn + warp_n * 64 + nt * 8 + 2 * tg;
            const float b0 = bias[col], b1 = bias[col + 1];
            if (OUT32) {
                float* C = (float*)Cout;
                *(float2*)(C + (size_t)row0 * N + col) =
                    make_float2(acc[mt][nt][0] + b0, acc[mt][nt][1] + b1);
                *(float2*)(C + (size_t)(row0 + 8) * N + col) =
                    make_float2(acc[mt][nt][2] + b0, acc[mt][nt][3] + b1);
            } else {
                __half* C = (__half*)Cout;
                *(uint32_t*)(C + (size_t)row0 * N + col) =
                    pack_h2(acc[mt][nt][0] + b0, acc[mt][nt][1] + b1);
                *(uint32_t*)(C + (size_t)(row0 + 8) * N + col) =
                    pack_h2(acc[mt][nt][2] + b0, acc[mt][nt][3] + b1);
            }
        }
    }
}

// ---------------------------------------------------------------------------
// fp16 flash attention (R13 shape): 128 q-rows/CTA, 128 threads, 4 warps,
// 2 CTAs/SM, double-buffered K/V, one barrier/iter, LDSM Q/K fragments.
// ONLY change vs R13: exp2 softmax with log2e folded into the Q scale.
// ---------------------------------------------------------------------------
#define QSTR 44
#define KSTR 44
#define VSTR 42
#define Q_U32 (128 * QSTR)             // 5632
#define K_U32 (64 * KSTR)              // 2816 per buffer
#define V_U32 (64 * VSTR)              // 2688 per buffer
#define ATT_SMEM_U32 (Q_U32 + 2 * K_U32 + 2 * V_U32)   // 16640 u32 = 66560 B

__global__ __launch_bounds__(128, 2)
void attention_tc(const __half* __restrict__ QKV, __half* __restrict__ C)
{
    extern __shared__ uint32_t sm[];
    uint32_t* Qs = sm;
    uint32_t* Vt = sm + Q_U32 + 2 * K_U32;
    const uint32_t smem_base = smem_u32ptr(sm);
    const uint32_t ks_base_b = smem_base + Q_U32 * 4;

    const int tid  = threadIdx.x;
    const int wid  = tid >> 5;
    const int lane = tid & 31;
    const int g    = lane >> 2;
    const int tg   = lane & 3;
    const int qb = blockIdx.x;
    const int h  = blockIdx.y;
    const int b  = blockIdx.z;
    const size_t baseQ = (size_t)b * SEQ * NQKV + h * DHEAD;
    const size_t baseK = baseQ + DMODEL;
    const size_t baseV = baseQ + 2 * DMODEL;
    const size_t baseC = (size_t)b * SEQ * DMODEL + h * DHEAD;
    const int wr = wid * 32;

    // scale = (1/8) * log2(e): softmax in exp2 domain
    const __half2 hscale = __floats2half2_rn(0.18033688f, 0.18033688f);

    const int kr = tid >> 3;
    const int kcnk = tid & 7;
    auto issue_K = [&](int kb, int buf) {
        const uint32_t kd = ks_base_b + (uint32_t)buf * K_U32 * 4;
#pragma unroll
        for (int i = 0; i < 4; i++) {
            const int key = kr + i * 16;
            cp_async16(kd + (uint32_t)(key * KSTR + kcnk * 4) * 4,
                       QKV + baseK + (size_t)(kb * 64 + key) * NQKV + kcnk * 8);
        }
        CP_COMMIT();
    };

    const int vp_p  = tid >> 4;
    const int vp_dc = tid & 15;
    auto ldg_V = [&](int kb, uint2* ea, uint2* eb) {
#pragma unroll
        for (int i = 0; i < 4; i++) {
            const int p = vp_p + i * 8;
            const __half* vb = QKV + baseV + (size_t)(kb * 64 + 2 * p) * NQKV + vp_dc * 4;
            ea[i] = *(const uint2*)(vb);
            eb[i] = *(const uint2*)(vb + NQKV);
        }
    };
    auto sts_V = [&](int buf, const uint2* ea, const uint2* eb) {
        uint32_t* vd = Vt + buf * V_U32;
#pragma unroll
        for (int i = 0; i < 4; i++) {
            const int p = vp_p + i * 8;
            __half2 ax = *(__half2*)&ea[i].x, ay = *(__half2*)&ea[i].y;
            __half2 bx = *(__half2*)&eb[i].x, by = *(__half2*)&eb[i].y;
            int pos = (p & ~7) + 2 * (p & 3) + ((p >> 2) & 1);
            __half2 o0 = __lows2half2(ax, bx), o1 = __highs2half2(ax, bx);
            __half2 o2 = __lows2half2(ay, by), o3 = __highs2half2(ay, by);
            vd[(vp_dc * 4 + 0) * VSTR + pos] = *(uint32_t*)&o0;
            vd[(vp_dc * 4 + 1) * VSTR + pos] = *(uint32_t*)&o1;
            vd[(vp_dc * 4 + 2) * VSTR + pos] = *(uint32_t*)&o2;
            vd[(vp_dc * 4 + 3) * VSTR + pos] = *(uint32_t*)&o3;
        }
    };

    // ---- prologue: issue K0, stage V0, stage Q (scaled) ----
    issue_K(0, 0);
    {
        uint2 ea[4], eb[4];
        ldg_V(0, ea, eb);
        sts_V(0, ea, eb);
    }
#pragma unroll
    for (int i = 0; i < 16; i++) {
        int t = tid + i * 128;
        int r = t >> 4, c = t & 15;
        uint2 v = *(const uint2*)(QKV + baseQ + (size_t)(qb * 128 + r) * NQKV + c * 4);
        __half2 a = __hmul2(*(__half2*)&v.x, hscale);
        __half2 bb = __hmul2(*(__half2*)&v.y, hscale);
        Qs[r * QSTR + c * 2 + 0] = *(uint32_t*)&a;
        Qs[r * QSTR + c * 2 + 1] = *(uint32_t*)&bb;
    }
    CP_WAIT(0);
    __syncthreads();

    // ---- hoist Q fragments via LDSM ----
    const uint32_t q_lane_off =
        (uint32_t)((wr + (lane & 15)) * QSTR) * 4 + (lane >> 4) * 16;
    uint32_t qf[2][4][4];
#pragma unroll
    for (int mt = 0; mt < 2; mt++)
#pragma unroll
        for (int ks = 0; ks < 4; ks++)
            ldsm_x4(qf[mt][ks][0], qf[mt][ks][1], qf[mt][ks][2], qf[mt][ks][3],
                    smem_base + q_lane_off + (uint32_t)(mt * 16 * QSTR) * 4 + ks * 32);

    const uint32_t k_lane_off =
        (uint32_t)(((lane & 7) + ((lane & 16) ? 8 : 0)) * KSTR) * 4
        + ((lane >> 3) & 1) * 16;

    float o[2][8][4];
#pragma unroll
    for (int mt = 0; mt < 2; mt++)
#pragma unroll
        for (int nt = 0; nt < 8; nt++)
#pragma unroll
            for (int q = 0; q < 4; q++) o[mt][nt][q] = 0.f;
    float mrow[2][2], lrow[2][2];
#pragma unroll
    for (int mt = 0; mt < 2; mt++) {
        mrow[mt][0] = mrow[mt][1] = -1e30f;
        lrow[mt][0] = lrow[mt][1] = 0.f;
    }

    for (int kb = 0; kb < SEQ / 64; kb++) {
        const int nb = (kb + 1) & 1;
        const bool more = (kb + 1 < SEQ / 64);
        if (more) issue_K(kb + 1, nb);
        else      CP_COMMIT();
        uint2 ea[4], eb[4];
        ldg_V(more ? kb + 1 : kb, ea, eb);

        const uint32_t kbuf = ks_base_b + (uint32_t)(kb & 1) * K_U32 * 4;
        const uint32_t* Vb = Vt + (kb & 1) * V_U32;

        // ---- S = Q @ K^T (exp2-domain scores) ----
        float s[2][8][4];
#pragma unroll
        for (int mt = 0; mt < 2; mt++)
#pragma unroll
            for (int nt = 0; nt < 8; nt++)
#pragma unroll
                for (int q = 0; q < 4; q++) s[mt][nt][q] = 0.f;

#pragma unroll
        for (int ks = 0; ks < 4; ks++) {
            uint32_t kf[4][4];
#pragma unroll
            for (int j = 0; j < 4; j++)
                ldsm_x4(kf[j][0], kf[j][1], kf[j][2], kf[j][3],
                        kbuf + k_lane_off + (uint32_t)(j * 16 * KSTR) * 4 + ks * 32);
#pragma unroll
            for (int nt = 0; nt < 8; nt++)
#pragma unroll
                for (int mt = 0; mt < 2; mt++)
                    mma_fp16(s[mt][nt],
                             qf[mt][ks][0], qf[mt][ks][1],
                             qf[mt][ks][2], qf[mt][ks][3],
                             kf[nt >> 1][(nt & 1) * 2],
                             kf[nt >> 1][(nt & 1) * 2 + 1]);
        }

        // ---- online softmax (exp2); P packed to half2 in registers ----
        uint32_t ph[2][8][2];
#pragma unroll
        for (int mt = 0; mt < 2; mt++) {
            float mx0 = -1e30f, mx1 = -1e30f;
#pragma unroll
            for (int nt = 0; nt < 8; nt++) {
                mx0 = fmaxf(mx0, fmaxf(s[mt][nt][0], s[mt][nt][1]));
                mx1 = fmaxf(mx1, fmaxf(s[mt][nt][2], s[mt][nt][3]));
            }
            mx0 = fmaxf(mx0, __shfl_xor_sync(0xffffffffu, mx0, 1));
            mx0 = fmaxf(mx0, __shfl_xor_sync(0xffffffffu, mx0, 2));
            mx1 = fmaxf(mx1, __shfl_xor_sync(0xffffffffu, mx1, 1));
            mx1 = fmaxf(mx1, __shfl_xor_sync(0xffffffffu, mx1, 2));
            const float mn0 = fmaxf(mrow[mt][0], mx0);
            const float mn1 = fmaxf(mrow[mt][1], mx1);
            const float al0 = fexp2(mrow[mt][0] - mn0);
            const float al1 = fexp2(mrow[mt][1] - mn1);
            mrow[mt][0] = mn0; mrow[mt][1] = mn1;

            float sum0 = 0.f, sum1 = 0.f;
#pragma unroll
            for (int nt = 0; nt < 8; nt++) {
                float p0 = fexp2(s[mt][nt][0] - mn0);
                float p1 = fexp2(s[mt][nt][1] - mn0);
                float p2 = fexp2(s[mt][nt][2] - mn1);
                float p3 = fexp2(s[mt][nt][3] - mn1);
                sum0 += p0 + p1; sum1 += p2 + p3;
                ph[mt][nt][0] = pack_h2(p0, p1);
                ph[mt][nt][1] = pack_h2(p2, p3);
                o[mt][nt][0] *= al0; o[mt][nt][1] *= al0;
                o[mt][nt][2] *= al1; o[mt][nt][3] *= al1;
            }
            sum0 += __shfl_xor_sync(0xffffffffu, sum0, 1);
            sum0 += __shfl_xor_sync(0xffffffffu, sum0, 2);
            sum1 += __shfl_xor_sync(0xffffffffu, sum1, 1);
            sum1 += __shfl_xor_sync(0xffffffffu, sum1, 2);
            lrow[mt][0] = lrow[mt][0] * al0 + sum0;
            lrow[mt][1] = lrow[mt][1] * al1 + sum1;
        }

        // ---- O += P @ V (register P; V pair-permutation matches ph) ----
#pragma unroll
        for (int kc = 0; kc < 4; kc++) {
            const int vcol = kc * 8 + 2 * tg;
#pragma unroll
            for (int nt = 0; nt < 8; nt++) {
                uint2 bf = *(const uint2*)&Vb[(nt * 8 + g) * VSTR + vcol];
#pragma unroll
                for (int mt = 0; mt < 2; mt++)
                    mma_fp16(o[mt][nt],
                             ph[mt][2 * kc][0], ph[mt][2 * kc][1],
                             ph[mt][2 * kc + 1][0], ph[mt][2 * kc + 1][1],
                             bf.x, bf.y);
            }
        }

        if (more) sts_V(nb, ea, eb);
        CP_WAIT(0);
        __syncthreads();
    }

    // ---- normalize + store ctx (half) ----
#pragma unroll
    for (int mt = 0; mt < 2; mt++) {
        const float li0 = 1.f / lrow[mt][0];
        const float li1 = 1.f / lrow[mt][1];
        const size_t r0 = baseC + (size_t)(qb * 128 + wr + mt * 16 + g) * DMODEL;
        const size_t r1 = r0 + (size_t)8 * DMODEL;
#pragma unroll
        for (int nt = 0; nt < 8; nt++) {
            const int col = nt * 8 + 2 * tg;
            *(uint32_t*)(C + r0 + col) = pack_h2(o[mt][nt][0] * li0, o[mt][nt][1] * li0);
            *(uint32_t*)(C + r1 + col) = pack_h2(o[mt][nt][2] * li1, o[mt][nt][3] * li1);
        }
    }
}

// ---------------------------------------------------------------------------
// Launch
// ---------------------------------------------------------------------------
extern "C" void kernel_launch(void* const* d_in, const int* in_sizes, int n_in,
                              void* d_out, int out_size)
{
    const float* X  = (const float*)d_in[0];
    const float* Wq = (const float*)d_in[1];
    const float* bq = (const float*)d_in[2];
    const float* Wk = (const float*)d_in[3];
    const float* bk = (const float*)d_in[4];
    const float* Wv = (const float*)d_in[5];
    const float* bv = (const float*)d_in[6];
    const float* Wo = (const float*)d_in[7];
    const float* bo = (const float*)d_in[8];
    float* out = (float*)d_out;

    __half *QKVp, *Cp, *Xh, *Wh;
    float* biasQKV;
    cudaGetSymbolAddress((void**)&QKVp, g_QKVh);
    cudaGetSymbolAddress((void**)&Cp, g_Ch);
    cudaGetSymbolAddress((void**)&Xh, g_Xh);
    cudaGetSymbolAddress((void**)&Wh, g_Wh);
    cudaGetSymbolAddress((void**)&biasQKV, g_biasQKV);
    __half* Wh0 = Wh;
    __half* Wh3 = Wh + 3 * (size_t)DMODEL * DMODEL;

    static bool attr_set = false;
    if (!attr_set) {
        cudaFuncSetAttribute(attention_tc,
                             cudaFuncAttributeMaxDynamicSharedMemorySize,
                             ATT_SMEM_U32 * (int)sizeof(uint32_t));
        cudaFuncSetAttribute(gemm_f16_nt<0>,
                             cudaFuncAttributeMaxDynamicSharedMemorySize,
                             GEMM_SMEM_BYTES);
        cudaFuncSetAttribute(gemm_f16_nt<1>,
                             cudaFuncAttributeMaxDynamicSharedMemorySize,
                             GEMM_SMEM_BYTES);
        attr_set = true;
    }

    cudaMemcpyAsync(biasQKV,            bq, DMODEL * sizeof(float), cudaMemcpyDeviceToDevice);
    cudaMemcpyAsync(biasQKV + DMODEL,   bk, DMODEL * sizeof(float), cudaMemcpyDeviceToDevice);
    cudaMemcpyAsync(biasQKV + 2*DMODEL, bv, DMODEL * sizeof(float), cudaMemcpyDeviceToDevice);

    const int XBLK = (MROWS * DMODEL) / (256 * 4);
    const int WBLK = (DMODEL * DMODEL) / (256 * 4);
    cvt_f32_f16<<<XBLK, 256>>>(X,  Xh);
    cvt_f32_f16<<<WBLK, 256>>>(Wq, Wh0);
    cvt_f32_f16<<<WBLK, 256>>>(Wk, Wh0 + (size_t)DMODEL * DMODEL);
    cvt_f32_f16<<<WBLK, 256>>>(Wv, Wh0 + 2 * (size_t)DMODEL * DMODEL);
    cvt_f32_f16<<<WBLK, 256>>>(Wo, Wh3);

    dim3 qkv_grid(NQKV / 128, MROWS / 128);      // (24, 128)
    gemm_f16_nt<0><<<qkv_grid, 128, GEMM_SMEM_BYTES>>>(
        Xh, Wh0, biasQKV, QKVp, MROWS, NQKV, DMODEL);

    dim3 att_grid(SEQ / 128, NHEAD, BATCH);      // (8, 16, 16)
    attention_tc<<<att_grid, 128, ATT_SMEM_U32 * sizeof(uint32_t)>>>(QKVp, Cp);

    dim3 o_grid(DMODEL / 128, MROWS / 128);      // (8, 128)
    gemm_f16_nt<1><<<o_grid, 128, GEMM_SMEM_BYTES>>>(
        Cp, Wh3, bo, out, MROWS, DMODEL, DMODEL);
}